// round 16
// baseline (speedup 1.0000x reference)
#include <cuda_runtime.h>
#include <cuda_bf16.h>
#include <cstdint>
#include <math.h>

#define DIM    1024
#define NH     16
#define HD     64
#define BATCH  2
#define SEQ    2048
#define M_TOT  (BATCH * SEQ)      // 4096
#define K3     (3 * DIM)          // 3072

// Q pre-scale: (1/8) * log2(e)  -> softmax exps become pure exp2
#define QSCALE 0.18033688011112042f

// Scratch (allocation-free rule)
__device__ __nv_bfloat16 g_a1[(size_t)M_TOT * K3];   // x split (K-concat)     [4096, 3072]
__device__ __nv_bfloat16 g_b1[(size_t)K3 * K3];      // W_qkv split (K-concat) [3072, 3072]
__device__ __nv_bfloat16 g_a2[(size_t)M_TOT * K3];   // attn-out split         [4096, 3072]
__device__ __nv_bfloat16 g_b2[(size_t)K3 * DIM];     // W_proj split           [3072, 1024]

// head-major bf16 hi/lo q,k,v : [b][h][s][d]
#define QKV_ELEMS ((size_t)BATCH * NH * SEQ * HD)
__device__ __nv_bfloat16 g_qh[QKV_ELEMS];
__device__ __nv_bfloat16 g_ql[QKV_ELEMS];
__device__ __nv_bfloat16 g_kh[QKV_ELEMS];
__device__ __nv_bfloat16 g_kl[QKV_ELEMS];
__device__ __nv_bfloat16 g_vh[QKV_ELEMS];
__device__ __nv_bfloat16 g_vl[QKV_ELEMS];

__device__ __forceinline__ uint32_t smem_u32(const void* p) {
    return (uint32_t)__cvta_generic_to_shared(p);
}
__device__ __forceinline__ void cpasync16(uint32_t dst, const void* src) {
    asm volatile("cp.async.cg.shared.global [%0], [%1], 16;\n" :: "r"(dst), "l"(src));
}

// Truncation-based hi/lo split of a float pair into two bf16x2 regs.
__device__ __forceinline__ void split_pack(float p0, float p1, uint32_t& hi, uint32_t& lo)
{
    uint32_t u0 = __float_as_uint(p0), u1 = __float_as_uint(p1);
    asm("prmt.b32 %0, %1, %2, 0x7632;" : "=r"(hi) : "r"(u0), "r"(u1));
    float h0 = __uint_as_float(u0 & 0xffff0000u);
    float h1 = __uint_as_float(u1 & 0xffff0000u);
    uint32_t l0 = __float_as_uint(p0 - h0);
    uint32_t l1 = __float_as_uint(p1 - h1);
    asm("prmt.b32 %0, %1, %2, 0x7632;" : "=r"(lo) : "r"(l0), "r"(l1));
}

// ---------------------------------------------------------------------------
// Splits (K-concat): A cols [0,K)=hi,[K,2K)=hi,[2K,3K)=lo ;
//                    B rows [0,K)=hi,[K,2K)=lo,[2K,3K)=hi
// ---------------------------------------------------------------------------
__global__ void split_a(const float4* __restrict__ in, __nv_bfloat16* __restrict__ out,
                        int M, int K)
{
    int i = blockIdx.x * blockDim.x + threadIdx.x;
    if (i >= M * K / 4) return;
    float4 v = in[i];
    int k = (i * 4) % K;
    size_t m = (size_t)((i * 4) / K);
    float f[4] = {v.x, v.y, v.z, v.w};
    __nv_bfloat16 hi[4], lo[4];
    #pragma unroll
    for (int j = 0; j < 4; j++) {
        hi[j] = __float2bfloat16(f[j]);
        lo[j] = __float2bfloat16(f[j] - __bfloat162float(hi[j]));
    }
    __nv_bfloat162 h0 = __halves2bfloat162(hi[0], hi[1]);
    __nv_bfloat162 h1 = __halves2bfloat162(hi[2], hi[3]);
    __nv_bfloat162 l0 = __halves2bfloat162(lo[0], lo[1]);
    __nv_bfloat162 l1 = __halves2bfloat162(lo[2], lo[3]);
    __nv_bfloat162* p0 = (__nv_bfloat162*)(out + m * 3 * K + k);
    __nv_bfloat162* p1 = (__nv_bfloat162*)(out + m * 3 * K + K + k);
    __nv_bfloat162* p2 = (__nv_bfloat162*)(out + m * 3 * K + 2 * K + k);
    p0[0] = h0; p0[1] = h1;
    p1[0] = h0; p1[1] = h1;
    p2[0] = l0; p2[1] = l1;
}

__global__ void split_b(const float4* __restrict__ in, __nv_bfloat16* __restrict__ out,
                        int K, int N)
{
    int i = blockIdx.x * blockDim.x + threadIdx.x;
    if (i >= K * N / 4) return;
    float4 v = in[i];
    int n = (i * 4) % N;
    size_t k = (size_t)((i * 4) / N);
    float f[4] = {v.x, v.y, v.z, v.w};
    __nv_bfloat16 hi[4], lo[4];
    #pragma unroll
    for (int j = 0; j < 4; j++) {
        hi[j] = __float2bfloat16(f[j]);
        lo[j] = __float2bfloat16(f[j] - __bfloat162float(hi[j]));
    }
    __nv_bfloat162 h0 = __halves2bfloat162(hi[0], hi[1]);
    __nv_bfloat162 h1 = __halves2bfloat162(hi[2], hi[3]);
    __nv_bfloat162 l0 = __halves2bfloat162(lo[0], lo[1]);
    __nv_bfloat162 l1 = __halves2bfloat162(lo[2], lo[3]);
    __nv_bfloat162* p0 = (__nv_bfloat162*)(out + k * N + n);
    __nv_bfloat162* p1 = (__nv_bfloat162*)(out + ((size_t)K + k) * N + n);
    __nv_bfloat162* p2 = (__nv_bfloat162*)(out + ((size_t)2 * K + k) * N + n);
    p0[0] = h0; p0[1] = h1;
    p1[0] = l0; p1[1] = l1;
    p2[0] = h0; p2[1] = h1;
}

// ---------------------------------------------------------------------------
// Pipelined bf16 mma.sync GEMM (unchanged).  CTA 128x128, 4 warps,
// warp tile 64x64, BK=64, 3-stage cp.async, 2 CTAs/SM.
// ---------------------------------------------------------------------------
#define GBN      128
#define GBK      64
#define AS_ELE   (128 * 72)
#define BS_ELE   (GBK * (GBN + 8))
#define STG_ELE  (AS_ELE + BS_ELE)
#define GEMM_SMEM (3 * STG_ELE * 2)

template <int MODE>
__global__ void __launch_bounds__(128, 2)
gemm_ms(const __nv_bfloat16* __restrict__ A, const __nv_bfloat16* __restrict__ B,
        const float* __restrict__ bias, float* __restrict__ C, int Ntot)
{
    extern __shared__ char dsm_raw[];
    __nv_bfloat16* dsm = (__nv_bfloat16*)dsm_raw;

    const int tid  = threadIdx.x;
    const int warp = tid >> 5;
    const int lane = tid & 31;
    const int wm = (warp >> 1) * 64;
    const int wn = (warp & 1) * 64;
    const int bm = blockIdx.y * 128;
    const int bn = blockIdx.x * GBN;

    const int ar = tid >> 3, ac = (tid & 7) * 8;
    const int br = tid >> 4, bc = (tid & 15) * 8;

    auto ldst = [&](int stage, int k0) {
        __nv_bfloat16* As = dsm + stage * STG_ELE;
        __nv_bfloat16* Bs = As + AS_ELE;
        #pragma unroll
        for (int i = 0; i < 8; i++) {
            int r = ar + i * 16;
            cpasync16(smem_u32(&As[r * 72 + ac]), &A[(size_t)(bm + r) * K3 + k0 + ac]);
        }
        #pragma unroll
        for (int i = 0; i < 8; i++) {
            int r = br + i * 8;
            cpasync16(smem_u32(&Bs[r * (GBN + 8) + bc]), &B[(size_t)(k0 + r) * Ntot + bn + bc]);
        }
        asm volatile("cp.async.commit_group;\n" ::: "memory");
    };

    float c[4][8][4];
    #pragma unroll
    for (int i = 0; i < 4; i++)
        #pragma unroll
        for (int j = 0; j < 8; j++)
            #pragma unroll
            for (int r = 0; r < 4; r++) c[i][j][r] = 0.f;

    const int NS = K3 / GBK;    // 48
    ldst(0, 0);
    ldst(1, GBK);

    for (int s = 0; s < NS; s++) {
        asm volatile("cp.async.wait_group 1;\n" ::: "memory");
        __syncthreads();
        if (s + 2 < NS) ldst((s + 2) % 3, (s + 2) * GBK);

        __nv_bfloat16* As = dsm + (s % 3) * STG_ELE;
        __nv_bfloat16* Bs = As + AS_ELE;

        #pragma unroll
        for (int kk = 0; kk < GBK; kk += 16) {
            uint32_t a[4][4], b[4][4];
            #pragma unroll
            for (int mi = 0; mi < 4; mi++) {
                uint32_t addr = smem_u32(&As[(wm + mi * 16 + (lane & 15)) * 72 +
                                             kk + ((lane >> 4) << 3)]);
                asm volatile("ldmatrix.sync.aligned.m8n8.x4.shared.b16 {%0,%1,%2,%3}, [%4];\n"
                    : "=r"(a[mi][0]), "=r"(a[mi][1]), "=r"(a[mi][2]), "=r"(a[mi][3])
                    : "r"(addr));
            }
            #pragma unroll
            for (int ni = 0; ni < 4; ni++) {
                uint32_t addr = smem_u32(&Bs[(kk + (lane & 15)) * (GBN + 8) +
                                             wn + ni * 16 + ((lane >> 4) << 3)]);
                asm volatile("ldmatrix.sync.aligned.m8n8.x4.trans.shared.b16 {%0,%1,%2,%3}, [%4];\n"
                    : "=r"(b[ni][0]), "=r"(b[ni][1]), "=r"(b[ni][2]), "=r"(b[ni][3])
                    : "r"(addr));
            }
            #pragma unroll
            for (int mi = 0; mi < 4; mi++) {
                #pragma unroll
                for (int nj = 0; nj < 8; nj++) {
                    uint32_t b0 = b[nj >> 1][(nj & 1) * 2 + 0];
                    uint32_t b1 = b[nj >> 1][(nj & 1) * 2 + 1];
                    asm volatile(
                        "mma.sync.aligned.m16n8k16.row.col.f32.bf16.bf16.f32 "
                        "{%0,%1,%2,%3}, {%4,%5,%6,%7}, {%8,%9}, {%0,%1,%2,%3};\n"
                        : "+f"(c[mi][nj][0]), "+f"(c[mi][nj][1]),
                          "+f"(c[mi][nj][2]), "+f"(c[mi][nj][3])
                        : "r"(a[mi][0]), "r"(a[mi][1]), "r"(a[mi][2]), "r"(a[mi][3]),
                          "r"(b0), "r"(b1));
                }
            }
        }
        __syncthreads();
    }

    #pragma unroll
    for (int mi = 0; mi < 4; mi++) {
        #pragma unroll
        for (int nj = 0; nj < 8; nj++) {
            int row = bm + wm + mi * 16 + (lane >> 2);
            int col = bn + wn + nj * 8 + (lane & 3) * 2;
            float bz0 = bias[col], bz1 = bias[col + 1];
            float v00 = c[mi][nj][0] + bz0, v01 = c[mi][nj][1] + bz1;
            float v10 = c[mi][nj][2] + bz0, v11 = c[mi][nj][3] + bz1;
            if (MODE == 0) {
                *(float2*)&C[(size_t)row * Ntot + col] = make_float2(v00, v01);
                *(float2*)&C[(size_t)(row + 8) * Ntot + col] = make_float2(v10, v11);
            } else {
                int p = col >> 10, r = col & 1023, h = r >> 6, d = r & 63;
                __nv_bfloat16* dh = (p == 0) ? g_qh : (p == 1) ? g_kh : g_vh;
                __nv_bfloat16* dl = (p == 0) ? g_ql : (p == 1) ? g_kl : g_vl;
                if (p == 0) { v00 *= QSCALE; v01 *= QSCALE; v10 *= QSCALE; v11 *= QSCALE; }
                #pragma unroll
                for (int half = 0; half < 2; half++) {
                    int tok = row + half * 8;
                    float a0 = half ? v10 : v00, a1 = half ? v11 : v01;
                    size_t dst = ((size_t)((tok >> 11) * NH + h) * SEQ + (tok & 2047)) * HD + d;
                    __nv_bfloat16 h0 = __float2bfloat16(a0), h1 = __float2bfloat16(a1);
                    __nv_bfloat16 l0 = __float2bfloat16(a0 - __bfloat162float(h0));
                    __nv_bfloat16 l1 = __float2bfloat16(a1 - __bfloat162float(h1));
                    *(__nv_bfloat162*)(dh + dst) = __halves2bfloat162(h0, h1);
                    *(__nv_bfloat162*)(dl + dst) = __halves2bfloat162(l0, l1);
                }
            }
        }
    }
}

// ---------------------------------------------------------------------------
// Flash attention: per-jp interleaved softmax+PV (exp2/pack of slice jp
// overlaps PV mma of earlier slices), deferred l-reduction (per-thread
// partials, quad-reduce once in epilogue), term-interleaved QK^T.
// ---------------------------------------------------------------------------
#define ATT_ARR  (64 * 72)
#define ATT_BUF  (4 * ATT_ARR)
#define ATT_SMEM (2 * ATT_BUF * 2)

__device__ __forceinline__ void mma16816(float* c, const uint32_t* a,
                                         uint32_t b0, uint32_t b1)
{
    asm volatile("mma.sync.aligned.m16n8k16.row.col.f32.bf16.bf16.f32 "
        "{%0,%1,%2,%3}, {%4,%5,%6,%7}, {%8,%9}, {%0,%1,%2,%3};\n"
        : "+f"(c[0]), "+f"(c[1]), "+f"(c[2]), "+f"(c[3])
        : "r"(a[0]), "r"(a[1]), "r"(a[2]), "r"(a[3]), "r"(b0), "r"(b1));
}
__device__ __forceinline__ void ldsm4(uint32_t* r, uint32_t addr)
{
    asm volatile("ldmatrix.sync.aligned.m8n8.x4.shared.b16 {%0,%1,%2,%3}, [%4];\n"
        : "=r"(r[0]), "=r"(r[1]), "=r"(r[2]), "=r"(r[3]) : "r"(addr));
}
__device__ __forceinline__ void ldsm4t(uint32_t* r, uint32_t addr)
{
    asm volatile("ldmatrix.sync.aligned.m8n8.x4.trans.shared.b16 {%0,%1,%2,%3}, [%4];\n"
        : "=r"(r[0]), "=r"(r[1]), "=r"(r[2]), "=r"(r[3]) : "r"(addr));
}

__global__ void __launch_bounds__(128, 3)
attn_tc(const __nv_bfloat16* __restrict__ qh, const __nv_bfloat16* __restrict__ ql,
        const __nv_bfloat16* __restrict__ kh, const __nv_bfloat16* __restrict__ kl,
        const __nv_bfloat16* __restrict__ vh, const __nv_bfloat16* __restrict__ vl,
        __nv_bfloat16* __restrict__ a2)
{
    extern __shared__ char dsm_raw[];
    __nv_bfloat16* dsm = (__nv_bfloat16*)dsm_raw;

    const int tid  = threadIdx.x;
    const int warp = tid >> 5;
    const int lane = tid & 31;
    const int q0   = blockIdx.x * 64;
    const size_t hbase = (size_t)(blockIdx.z * NH + blockIdx.y) * SEQ * HD;

    auto prefetch = [&](int kt, int buf) {
        __nv_bfloat16* B = dsm + buf * ATT_BUF;
        const size_t tb = hbase + (size_t)kt * 64 * HD;
        #pragma unroll
        for (int i = 0; i < 4; i++) {
            int idx = i * 128 + tid;
            int r = idx >> 3, cc = (idx & 7) * 8;
            size_t g = tb + (size_t)r * HD + cc;
            int sm = r * 72 + cc;
            cpasync16(smem_u32(&B[sm]),               kh + g);
            cpasync16(smem_u32(&B[ATT_ARR + sm]),     kl + g);
            cpasync16(smem_u32(&B[2 * ATT_ARR + sm]), vh + g);
            cpasync16(smem_u32(&B[3 * ATT_ARR + sm]), vl + g);
        }
        asm volatile("cp.async.commit_group;\n" ::: "memory");
    };

    prefetch(0, 0);

    uint32_t qa_h[4][4], qa_l[4][4];
    {
        const int qrow = q0 + warp * 16 + (lane >> 2);
        const __nv_bfloat16* ph = qh + hbase + (size_t)qrow * HD + (lane & 3) * 2;
        const __nv_bfloat16* pl = ql + hbase + (size_t)qrow * HD + (lane & 3) * 2;
        #pragma unroll
        for (int ks = 0; ks < 4; ks++) {
            qa_h[ks][0] = *(const uint32_t*)(ph + ks * 16);
            qa_h[ks][1] = *(const uint32_t*)(ph + 8 * HD + ks * 16);
            qa_h[ks][2] = *(const uint32_t*)(ph + ks * 16 + 8);
            qa_h[ks][3] = *(const uint32_t*)(ph + 8 * HD + ks * 16 + 8);
            qa_l[ks][0] = *(const uint32_t*)(pl + ks * 16);
            qa_l[ks][1] = *(const uint32_t*)(pl + 8 * HD + ks * 16);
            qa_l[ks][2] = *(const uint32_t*)(pl + ks * 16 + 8);
            qa_l[ks][3] = *(const uint32_t*)(pl + 8 * HD + ks * 16 + 8);
        }
    }

    float o[8][4];
    #pragma unroll
    for (int j = 0; j < 8; j++)
        #pragma unroll
        for (int r = 0; r < 4; r++) o[j][r] = 0.f;
    // lA/lB: per-thread PARTIAL row sums (quad-reduced once at the end).
    float mA = -INFINITY, mB = -INFINITY, lA = 0.f, lB = 0.f;

    const int lkn = ((lane >> 4) << 3) + (lane & 7);
    const int lkk = ((lane >> 3) & 1) * 8;
    const int lvr = lane & 15;
    const int lvc = (lane >> 4) << 3;

    for (int kt = 0; kt < SEQ / 64; kt++) {
        asm volatile("cp.async.wait_group 0;\n" ::: "memory");
        __syncthreads();
        if (kt + 1 < SEQ / 64) prefetch(kt + 1, (kt + 1) & 1);

        __nv_bfloat16* Ksh = dsm + (kt & 1) * ATT_BUF;
        __nv_bfloat16* Ksl = Ksh + ATT_ARR;
        __nv_bfloat16* Vsh = Ksh + 2 * ATT_ARR;
        __nv_bfloat16* Vsl = Ksh + 3 * ATT_ARR;

        float s[8][4];
        #pragma unroll
        for (int j = 0; j < 8; j++)
            #pragma unroll
            for (int r = 0; r < 4; r++) s[j][r] = 0.f;

        // ---- S = Q K^T, term-interleaved ----
        #pragma unroll
        for (int ks = 0; ks < 4; ks++) {
            uint32_t bh[4][4], bl[4][4];
            #pragma unroll
            for (int np = 0; np < 4; np++) {
                ldsm4(bh[np], smem_u32(&Ksh[(np * 16 + lkn) * 72 + ks * 16 + lkk]));
                ldsm4(bl[np], smem_u32(&Ksl[(np * 16 + lkn) * 72 + ks * 16 + lkk]));
            }
            #pragma unroll
            for (int np = 0; np < 4; np++) {
                mma16816(s[np * 2],     qa_h[ks], bh[np][0], bh[np][1]);
                mma16816(s[np * 2 + 1], qa_h[ks], bh[np][2], bh[np][3]);
            }
            #pragma unroll
            for (int np = 0; np < 4; np++) {
                mma16816(s[np * 2],     qa_l[ks], bh[np][0], bh[np][1]);
                mma16816(s[np * 2 + 1], qa_l[ks], bh[np][2], bh[np][3]);
            }
            #pragma unroll
            for (int np = 0; np < 4; np++) {
                mma16816(s[np * 2],     qa_h[ks], bl[np][0], bl[np][1]);
                mma16816(s[np * 2 + 1], qa_h[ks], bl[np][2], bl[np][3]);
            }
        }

        // ---- quad max (needed before any exp2) ----
        float mxA = -INFINITY, mxB = -INFINITY;
        #pragma unroll
        for (int j = 0; j < 8; j++) {
            mxA = fmaxf(mxA, fmaxf(s[j][0], s[j][1]));
            mxB = fmaxf(mxB, fmaxf(s[j][2], s[j][3]));
        }
        mxA = fmaxf(mxA, __shfl_xor_sync(0xffffffffu, mxA, 1));
        mxA = fmaxf(mxA, __shfl_xor_sync(0xffffffffu, mxA, 2));
        mxB = fmaxf(mxB, __shfl_xor_sync(0xffffffffu, mxB, 1));
        mxB = fmaxf(mxB, __shfl_xor_sync(0xffffffffu, mxB, 2));

        float mA_new = fmaxf(mA, mxA), mB_new = fmaxf(mB, mxB);
        float cA = exp2f(mA - mA_new), cB = exp2f(mB - mB_new);
        lA *= cA;  lB *= cB;
        mA = mA_new;  mB = mB_new;

        #pragma unroll
        for (int j = 0; j < 8; j++) {
            o[j][0] *= cA; o[j][1] *= cA;
            o[j][2] *= cB; o[j][3] *= cB;
        }

        // ---- per-jp: softmax slice + its PV mmas (overlap MUFU with HMMA) ----
        #pragma unroll
        for (int jp = 0; jp < 4; jp++) {
            uint32_t ph_[4], pl_[4];
            #pragma unroll
            for (int half = 0; half < 2; half++) {
                int t = jp * 2 + half;
                float p0 = exp2f(s[t][0] - mA_new);
                float p1 = exp2f(s[t][1] - mA_new);
                float p2 = exp2f(s[t][2] - mB_new);
                float p3 = exp2f(s[t][3] - mB_new);
                lA += p0 + p1;
                lB += p2 + p3;
                split_pack(p0, p1, ph_[half * 2 + 0], pl_[half * 2 + 0]);
                split_pack(p2, p3, ph_[half * 2 + 1], pl_[half * 2 + 1]);
            }
            uint32_t bh[4][4], bl[4][4];
            #pragma unroll
            for (int nv = 0; nv < 4; nv++) {
                ldsm4t(bh[nv], smem_u32(&Vsh[(jp * 16 + lvr) * 72 + nv * 16 + lvc]));
                ldsm4t(bl[nv], smem_u32(&Vsl[(jp * 16 + lvr) * 72 + nv * 16 + lvc]));
            }
            #pragma unroll
            for (int nv = 0; nv < 4; nv++) {
                mma16816(o[nv * 2],     ph_, bh[nv][0], bh[nv][1]);
                mma16816(o[nv * 2 + 1], ph_, bh[nv][2], bh[nv][3]);
            }
            #pragma unroll
            for (int nv = 0; nv < 4; nv++) {
                mma16816(o[nv * 2],     pl_, bh[nv][0], bh[nv][1]);
                mma16816(o[nv * 2 + 1], pl_, bh[nv][2], bh[nv][3]);
            }
            #pragma unroll
            for (int nv = 0; nv < 4; nv++) {
                mma16816(o[nv * 2],     ph_, bl[nv][0], bl[nv][1]);
                mma16816(o[nv * 2 + 1], ph_, bl[nv][2], bl[nv][3]);
            }
        }
        // no end-of-iter barrier: top-of-iter wait_group+bar orders buffer reuse
    }

    // ---- quad-reduce the deferred l partials, then epilogue ----
    lA += __shfl_xor_sync(0xffffffffu, lA, 1);
    lA += __shfl_xor_sync(0xffffffffu, lA, 2);
    lB += __shfl_xor_sync(0xffffffffu, lB, 1);
    lB += __shfl_xor_sync(0xffffffffu, lB, 2);

    const float iA = 1.f / lA, iB = 1.f / lB;
    const int row = q0 + warp * 16 + (lane >> 2);
    const int c0 = blockIdx.y * HD + (lane & 3) * 2;
    #pragma unroll
    for (int half = 0; half < 2; half++) {
        size_t tok = (size_t)blockIdx.z * SEQ + row + half * 8;
        __nv_bfloat16* base = a2 + tok * K3;
        float inv = half ? iB : iA;
        #pragma unroll
        for (int j = 0; j < 8; j++) {
            float a0 = o[j][half * 2 + 0] * inv;
            float a1 = o[j][half * 2 + 1] * inv;
            uint32_t hv, lv;
            split_pack(a0, a1, hv, lv);
            int cc = c0 + j * 8;
            *(uint32_t*)(base + cc)            = hv;
            *(uint32_t*)(base + DIM + cc)      = hv;
            *(uint32_t*)(base + 2 * DIM + cc)  = lv;
        }
    }
}

// ---------------------------------------------------------------------------

extern "C" void kernel_launch(void* const* d_in, const int* in_sizes, int n_in,
                              void* d_out, int out_size)
{
    const float* x      = (const float*)d_in[0];
    const float* W_qkv  = (const float*)d_in[1];
    const float* b_qkv  = (const float*)d_in[2];
    const float* W_proj = (const float*)d_in[3];
    const float* b_proj = (const float*)d_in[4];
    float* out = (float*)d_out;

    __nv_bfloat16 *a1, *b1, *a2, *b2;
    cudaGetSymbolAddress((void**)&a1, g_a1);
    cudaGetSymbolAddress((void**)&b1, g_b1);
    cudaGetSymbolAddress((void**)&a2, g_a2);
    cudaGetSymbolAddress((void**)&b2, g_b2);
    __nv_bfloat16 *qh, *ql, *kh, *kl, *vh, *vl;
    cudaGetSymbolAddress((void**)&qh, g_qh);
    cudaGetSymbolAddress((void**)&ql, g_ql);
    cudaGetSymbolAddress((void**)&kh, g_kh);
    cudaGetSymbolAddress((void**)&kl, g_kl);
    cudaGetSymbolAddress((void**)&vh, g_vh);
    cudaGetSymbolAddress((void**)&vl, g_vl);

    cudaFuncSetAttribute(gemm_ms<0>, cudaFuncAttributeMaxDynamicSharedMemorySize, GEMM_SMEM);
    cudaFuncSetAttribute(gemm_ms<1>, cudaFuncAttributeMaxDynamicSharedMemorySize, GEMM_SMEM);
    cudaFuncSetAttribute(attn_tc,    cudaFuncAttributeMaxDynamicSharedMemorySize, ATT_SMEM);

    // 1) splits for gemm1
    split_a<<<(M_TOT * DIM / 4) / 256, 256>>>((const float4*)x, a1, M_TOT, DIM);
    split_b<<<(DIM * K3 / 4) / 256, 256>>>((const float4*)W_qkv, b1, DIM, K3);

    // 2) qkv = x @ W_qkv + b_qkv, fused hi/lo head-major scatter (q *= QSCALE)
    {
        dim3 grid(K3 / GBN, M_TOT / 128);
        gemm_ms<1><<<grid, 128, GEMM_SMEM>>>(a1, b1, b_qkv, nullptr, K3);
    }

    // 3) attention, fused K-concat hi/lo epilogue -> a2
    {
        dim3 grid(SEQ / 64, NH, BATCH);
        attn_tc<<<grid, 128, ATT_SMEM>>>(qh, ql, kh, kl, vh, vl, a2);
    }

    // 4) W_proj split
    split_b<<<(DIM * DIM / 4) / 256, 256>>>((const float4*)W_proj, b2, DIM, DIM);

    // 5) out = attn @ W_proj + b_proj
    {
        dim3 grid(DIM / GBN, M_TOT / 128);
        gemm_ms<0><<<grid, 128, GEMM_SMEM>>>(a2, b2, b_proj, out, DIM);
    }
}

// round 17
// speedup vs baseline: 1.5453x; 1.5453x over previous
#include <cuda_runtime.h>
#include <cuda_bf16.h>
#include <cstdint>
#include <math.h>

#define DIM    1024
#define NH     16
#define HD     64
#define BATCH  2
#define SEQ    2048
#define M_TOT  (BATCH * SEQ)      // 4096
#define K3     (3 * DIM)          // 3072

// Q pre-scale: (1/8) * log2(e)  -> softmax exps become pure exp2
#define QSCALE 0.18033688011112042f

// Scratch (allocation-free rule)
__device__ __nv_bfloat16 g_a1[(size_t)M_TOT * K3];   // x split (K-concat)     [4096, 3072]
__device__ __nv_bfloat16 g_b1[(size_t)K3 * K3];      // W_qkv split (K-concat) [3072, 3072]
__device__ __nv_bfloat16 g_a2[(size_t)M_TOT * K3];   // attn-out split         [4096, 3072]
__device__ __nv_bfloat16 g_b2[(size_t)K3 * DIM];     // W_proj split           [3072, 1024]

// head-major bf16 hi/lo q,k,v : [b][h][s][d]
#define QKV_ELEMS ((size_t)BATCH * NH * SEQ * HD)
__device__ __nv_bfloat16 g_qh[QKV_ELEMS];
__device__ __nv_bfloat16 g_ql[QKV_ELEMS];
__device__ __nv_bfloat16 g_kh[QKV_ELEMS];
__device__ __nv_bfloat16 g_kl[QKV_ELEMS];
__device__ __nv_bfloat16 g_vh[QKV_ELEMS];
__device__ __nv_bfloat16 g_vl[QKV_ELEMS];

__device__ __forceinline__ uint32_t smem_u32(const void* p) {
    return (uint32_t)__cvta_generic_to_shared(p);
}
__device__ __forceinline__ void cpasync16(uint32_t dst, const void* src) {
    asm volatile("cp.async.cg.shared.global [%0], [%1], 16;\n" :: "r"(dst), "l"(src));
}

// Truncation-based hi/lo split of a float pair into two bf16x2 regs.
__device__ __forceinline__ void split_pack(float p0, float p1, uint32_t& hi, uint32_t& lo)
{
    uint32_t u0 = __float_as_uint(p0), u1 = __float_as_uint(p1);
    asm("prmt.b32 %0, %1, %2, 0x7632;" : "=r"(hi) : "r"(u0), "r"(u1));
    float h0 = __uint_as_float(u0 & 0xffff0000u);
    float h1 = __uint_as_float(u1 & 0xffff0000u);
    uint32_t l0 = __float_as_uint(p0 - h0);
    uint32_t l1 = __float_as_uint(p1 - h1);
    asm("prmt.b32 %0, %1, %2, 0x7632;" : "=r"(lo) : "r"(l0), "r"(l1));
}

// ---------------------------------------------------------------------------
// Splits (K-concat): A cols [0,K)=hi,[K,2K)=hi,[2K,3K)=lo ;
//                    B rows [0,K)=hi,[K,2K)=lo,[2K,3K)=hi
// ---------------------------------------------------------------------------
__global__ void split_a(const float4* __restrict__ in, __nv_bfloat16* __restrict__ out,
                        int M, int K)
{
    int i = blockIdx.x * blockDim.x + threadIdx.x;
    if (i >= M * K / 4) return;
    float4 v = in[i];
    int k = (i * 4) % K;
    size_t m = (size_t)((i * 4) / K);
    float f[4] = {v.x, v.y, v.z, v.w};
    __nv_bfloat16 hi[4], lo[4];
    #pragma unroll
    for (int j = 0; j < 4; j++) {
        hi[j] = __float2bfloat16(f[j]);
        lo[j] = __float2bfloat16(f[j] - __bfloat162float(hi[j]));
    }
    __nv_bfloat162 h0 = __halves2bfloat162(hi[0], hi[1]);
    __nv_bfloat162 h1 = __halves2bfloat162(hi[2], hi[3]);
    __nv_bfloat162 l0 = __halves2bfloat162(lo[0], lo[1]);
    __nv_bfloat162 l1 = __halves2bfloat162(lo[2], lo[3]);
    __nv_bfloat162* p0 = (__nv_bfloat162*)(out + m * 3 * K + k);
    __nv_bfloat162* p1 = (__nv_bfloat162*)(out + m * 3 * K + K + k);
    __nv_bfloat162* p2 = (__nv_bfloat162*)(out + m * 3 * K + 2 * K + k);
    p0[0] = h0; p0[1] = h1;
    p1[0] = h0; p1[1] = h1;
    p2[0] = l0; p2[1] = l1;
}

__global__ void split_b(const float4* __restrict__ in, __nv_bfloat16* __restrict__ out,
                        int K, int N)
{
    int i = blockIdx.x * blockDim.x + threadIdx.x;
    if (i >= K * N / 4) return;
    float4 v = in[i];
    int n = (i * 4) % N;
    size_t k = (size_t)((i * 4) / N);
    float f[4] = {v.x, v.y, v.z, v.w};
    __nv_bfloat16 hi[4], lo[4];
    #pragma unroll
    for (int j = 0; j < 4; j++) {
        hi[j] = __float2bfloat16(f[j]);
        lo[j] = __float2bfloat16(f[j] - __bfloat162float(hi[j]));
    }
    __nv_bfloat162 h0 = __halves2bfloat162(hi[0], hi[1]);
    __nv_bfloat162 h1 = __halves2bfloat162(hi[2], hi[3]);
    __nv_bfloat162 l0 = __halves2bfloat162(lo[0], lo[1]);
    __nv_bfloat162 l1 = __halves2bfloat162(lo[2], lo[3]);
    __nv_bfloat162* p0 = (__nv_bfloat162*)(out + k * N + n);
    __nv_bfloat162* p1 = (__nv_bfloat162*)(out + ((size_t)K + k) * N + n);
    __nv_bfloat162* p2 = (__nv_bfloat162*)(out + ((size_t)2 * K + k) * N + n);
    p0[0] = h0; p0[1] = h1;
    p1[0] = l0; p1[1] = l1;
    p2[0] = h0; p2[1] = h1;
}

// ---------------------------------------------------------------------------
// Pipelined bf16 mma.sync GEMM (unchanged from R14/R15).  CTA 128x128,
// 4 warps, warp tile 64x64, BK=64, 3-stage cp.async, 2 CTAs/SM.
// ---------------------------------------------------------------------------
#define GBN      128
#define GBK      64
#define AS_ELE   (128 * 72)
#define BS_ELE   (GBK * (GBN + 8))
#define STG_ELE  (AS_ELE + BS_ELE)
#define GEMM_SMEM (3 * STG_ELE * 2)

template <int MODE>
__global__ void __launch_bounds__(128, 2)
gemm_ms(const __nv_bfloat16* __restrict__ A, const __nv_bfloat16* __restrict__ B,
        const float* __restrict__ bias, float* __restrict__ C, int Ntot)
{
    extern __shared__ char dsm_raw[];
    __nv_bfloat16* dsm = (__nv_bfloat16*)dsm_raw;

    const int tid  = threadIdx.x;
    const int warp = tid >> 5;
    const int lane = tid & 31;
    const int wm = (warp >> 1) * 64;
    const int wn = (warp & 1) * 64;
    const int bm = blockIdx.y * 128;
    const int bn = blockIdx.x * GBN;

    const int ar = tid >> 3, ac = (tid & 7) * 8;
    const int br = tid >> 4, bc = (tid & 15) * 8;

    auto ldst = [&](int stage, int k0) {
        __nv_bfloat16* As = dsm + stage * STG_ELE;
        __nv_bfloat16* Bs = As + AS_ELE;
        #pragma unroll
        for (int i = 0; i < 8; i++) {
            int r = ar + i * 16;
            cpasync16(smem_u32(&As[r * 72 + ac]), &A[(size_t)(bm + r) * K3 + k0 + ac]);
        }
        #pragma unroll
        for (int i = 0; i < 8; i++) {
            int r = br + i * 8;
            cpasync16(smem_u32(&Bs[r * (GBN + 8) + bc]), &B[(size_t)(k0 + r) * Ntot + bn + bc]);
        }
        asm volatile("cp.async.commit_group;\n" ::: "memory");
    };

    float c[4][8][4];
    #pragma unroll
    for (int i = 0; i < 4; i++)
        #pragma unroll
        for (int j = 0; j < 8; j++)
            #pragma unroll
            for (int r = 0; r < 4; r++) c[i][j][r] = 0.f;

    const int NS = K3 / GBK;    // 48
    ldst(0, 0);
    ldst(1, GBK);

    for (int s = 0; s < NS; s++) {
        asm volatile("cp.async.wait_group 1;\n" ::: "memory");
        __syncthreads();
        if (s + 2 < NS) ldst((s + 2) % 3, (s + 2) * GBK);

        __nv_bfloat16* As = dsm + (s % 3) * STG_ELE;
        __nv_bfloat16* Bs = As + AS_ELE;

        #pragma unroll
        for (int kk = 0; kk < GBK; kk += 16) {
            uint32_t a[4][4], b[4][4];
            #pragma unroll
            for (int mi = 0; mi < 4; mi++) {
                uint32_t addr = smem_u32(&As[(wm + mi * 16 + (lane & 15)) * 72 +
                                             kk + ((lane >> 4) << 3)]);
                asm volatile("ldmatrix.sync.aligned.m8n8.x4.shared.b16 {%0,%1,%2,%3}, [%4];\n"
                    : "=r"(a[mi][0]), "=r"(a[mi][1]), "=r"(a[mi][2]), "=r"(a[mi][3])
                    : "r"(addr));
            }
            #pragma unroll
            for (int ni = 0; ni < 4; ni++) {
                uint32_t addr = smem_u32(&Bs[(kk + (lane & 15)) * (GBN + 8) +
                                             wn + ni * 16 + ((lane >> 4) << 3)]);
                asm volatile("ldmatrix.sync.aligned.m8n8.x4.trans.shared.b16 {%0,%1,%2,%3}, [%4];\n"
                    : "=r"(b[ni][0]), "=r"(b[ni][1]), "=r"(b[ni][2]), "=r"(b[ni][3])
                    : "r"(addr));
            }
            #pragma unroll
            for (int mi = 0; mi < 4; mi++) {
                #pragma unroll
                for (int nj = 0; nj < 8; nj++) {
                    uint32_t b0 = b[nj >> 1][(nj & 1) * 2 + 0];
                    uint32_t b1 = b[nj >> 1][(nj & 1) * 2 + 1];
                    asm volatile(
                        "mma.sync.aligned.m16n8k16.row.col.f32.bf16.bf16.f32 "
                        "{%0,%1,%2,%3}, {%4,%5,%6,%7}, {%8,%9}, {%0,%1,%2,%3};\n"
                        : "+f"(c[mi][nj][0]), "+f"(c[mi][nj][1]),
                          "+f"(c[mi][nj][2]), "+f"(c[mi][nj][3])
                        : "r"(a[mi][0]), "r"(a[mi][1]), "r"(a[mi][2]), "r"(a[mi][3]),
                          "r"(b0), "r"(b1));
                }
            }
        }
        __syncthreads();
    }

    #pragma unroll
    for (int mi = 0; mi < 4; mi++) {
        #pragma unroll
        for (int nj = 0; nj < 8; nj++) {
            int row = bm + wm + mi * 16 + (lane >> 2);
            int col = bn + wn + nj * 8 + (lane & 3) * 2;
            float bz0 = bias[col], bz1 = bias[col + 1];
            float v00 = c[mi][nj][0] + bz0, v01 = c[mi][nj][1] + bz1;
            float v10 = c[mi][nj][2] + bz0, v11 = c[mi][nj][3] + bz1;
            if (MODE == 0) {
                *(float2*)&C[(size_t)row * Ntot + col] = make_float2(v00, v01);
                *(float2*)&C[(size_t)(row + 8) * Ntot + col] = make_float2(v10, v11);
            } else {
                int p = col >> 10, r = col & 1023, h = r >> 6, d = r & 63;
                __nv_bfloat16* dh = (p == 0) ? g_qh : (p == 1) ? g_kh : g_vh;
                __nv_bfloat16* dl = (p == 0) ? g_ql : (p == 1) ? g_kl : g_vl;
                if (p == 0) { v00 *= QSCALE; v01 *= QSCALE; v10 *= QSCALE; v11 *= QSCALE; }
                #pragma unroll
                for (int half = 0; half < 2; half++) {
                    int tok = row + half * 8;
                    float a0 = half ? v10 : v00, a1 = half ? v11 : v01;
                    size_t dst = ((size_t)((tok >> 11) * NH + h) * SEQ + (tok & 2047)) * HD + d;
                    __nv_bfloat16 h0 = __float2bfloat16(a0), h1 = __float2bfloat16(a1);
                    __nv_bfloat16 l0 = __float2bfloat16(a0 - __bfloat162float(h0));
                    __nv_bfloat16 l1 = __float2bfloat16(a1 - __bfloat162float(h1));
                    *(__nv_bfloat162*)(dh + dst) = __halves2bfloat162(h0, h1);
                    *(__nv_bfloat162*)(dl + dst) = __halves2bfloat162(l0, l1);
                }
            }
        }
    }
}

// ---------------------------------------------------------------------------
// Flash attention (R15 structure): term-interleaved mma, exp2 softmax with
// PRMT trunc-split packing, deferred l-reduction (single quad-reduce in the
// epilogue — the only change vs R15), fused a2 epilogue.
// ---------------------------------------------------------------------------
#define ATT_ARR  (64 * 72)
#define ATT_BUF  (4 * ATT_ARR)
#define ATT_SMEM (2 * ATT_BUF * 2)

__device__ __forceinline__ void mma16816(float* c, const uint32_t* a,
                                         uint32_t b0, uint32_t b1)
{
    asm volatile("mma.sync.aligned.m16n8k16.row.col.f32.bf16.bf16.f32 "
        "{%0,%1,%2,%3}, {%4,%5,%6,%7}, {%8,%9}, {%0,%1,%2,%3};\n"
        : "+f"(c[0]), "+f"(c[1]), "+f"(c[2]), "+f"(c[3])
        : "r"(a[0]), "r"(a[1]), "r"(a[2]), "r"(a[3]), "r"(b0), "r"(b1));
}
__device__ __forceinline__ void ldsm4(uint32_t* r, uint32_t addr)
{
    asm volatile("ldmatrix.sync.aligned.m8n8.x4.shared.b16 {%0,%1,%2,%3}, [%4];\n"
        : "=r"(r[0]), "=r"(r[1]), "=r"(r[2]), "=r"(r[3]) : "r"(addr));
}
__device__ __forceinline__ void ldsm4t(uint32_t* r, uint32_t addr)
{
    asm volatile("ldmatrix.sync.aligned.m8n8.x4.trans.shared.b16 {%0,%1,%2,%3}, [%4];\n"
        : "=r"(r[0]), "=r"(r[1]), "=r"(r[2]), "=r"(r[3]) : "r"(addr));
}

__global__ void __launch_bounds__(128, 3)
attn_tc(const __nv_bfloat16* __restrict__ qh, const __nv_bfloat16* __restrict__ ql,
        const __nv_bfloat16* __restrict__ kh, const __nv_bfloat16* __restrict__ kl,
        const __nv_bfloat16* __restrict__ vh, const __nv_bfloat16* __restrict__ vl,
        __nv_bfloat16* __restrict__ a2)
{
    extern __shared__ char dsm_raw[];
    __nv_bfloat16* dsm = (__nv_bfloat16*)dsm_raw;

    const int tid  = threadIdx.x;
    const int warp = tid >> 5;
    const int lane = tid & 31;
    const int q0   = blockIdx.x * 64;
    const size_t hbase = (size_t)(blockIdx.z * NH + blockIdx.y) * SEQ * HD;

    auto prefetch = [&](int kt, int buf) {
        __nv_bfloat16* B = dsm + buf * ATT_BUF;
        const size_t tb = hbase + (size_t)kt * 64 * HD;
        #pragma unroll
        for (int i = 0; i < 4; i++) {
            int idx = i * 128 + tid;
            int r = idx >> 3, cc = (idx & 7) * 8;
            size_t g = tb + (size_t)r * HD + cc;
            int sm = r * 72 + cc;
            cpasync16(smem_u32(&B[sm]),               kh + g);
            cpasync16(smem_u32(&B[ATT_ARR + sm]),     kl + g);
            cpasync16(smem_u32(&B[2 * ATT_ARR + sm]), vh + g);
            cpasync16(smem_u32(&B[3 * ATT_ARR + sm]), vl + g);
        }
        asm volatile("cp.async.commit_group;\n" ::: "memory");
    };

    prefetch(0, 0);

    uint32_t qa_h[4][4], qa_l[4][4];
    {
        const int qrow = q0 + warp * 16 + (lane >> 2);
        const __nv_bfloat16* ph = qh + hbase + (size_t)qrow * HD + (lane & 3) * 2;
        const __nv_bfloat16* pl = ql + hbase + (size_t)qrow * HD + (lane & 3) * 2;
        #pragma unroll
        for (int ks = 0; ks < 4; ks++) {
            qa_h[ks][0] = *(const uint32_t*)(ph + ks * 16);
            qa_h[ks][1] = *(const uint32_t*)(ph + 8 * HD + ks * 16);
            qa_h[ks][2] = *(const uint32_t*)(ph + ks * 16 + 8);
            qa_h[ks][3] = *(const uint32_t*)(ph + 8 * HD + ks * 16 + 8);
            qa_l[ks][0] = *(const uint32_t*)(pl + ks * 16);
            qa_l[ks][1] = *(const uint32_t*)(pl + 8 * HD + ks * 16);
            qa_l[ks][2] = *(const uint32_t*)(pl + ks * 16 + 8);
            qa_l[ks][3] = *(const uint32_t*)(pl + 8 * HD + ks * 16 + 8);
        }
    }

    float o[8][4];
    #pragma unroll
    for (int j = 0; j < 8; j++)
        #pragma unroll
        for (int r = 0; r < 4; r++) o[j][r] = 0.f;
    // lA/lB hold per-thread PARTIAL row sums; quad-reduced once in epilogue.
    float mA = -INFINITY, mB = -INFINITY, lA = 0.f, lB = 0.f;

    const int lkn = ((lane >> 4) << 3) + (lane & 7);
    const int lkk = ((lane >> 3) & 1) * 8;
    const int lvr = lane & 15;
    const int lvc = (lane >> 4) << 3;

    for (int kt = 0; kt < SEQ / 64; kt++) {
        asm volatile("cp.async.wait_group 0;\n" ::: "memory");
        __syncthreads();
        if (kt + 1 < SEQ / 64) prefetch(kt + 1, (kt + 1) & 1);

        __nv_bfloat16* Ksh = dsm + (kt & 1) * ATT_BUF;
        __nv_bfloat16* Ksl = Ksh + ATT_ARR;
        __nv_bfloat16* Vsh = Ksh + 2 * ATT_ARR;
        __nv_bfloat16* Vsl = Ksh + 3 * ATT_ARR;

        float s[8][4];
        #pragma unroll
        for (int j = 0; j < 8; j++)
            #pragma unroll
            for (int r = 0; r < 4; r++) s[j][r] = 0.f;

        // ---- S = Q K^T, term-interleaved ----
        #pragma unroll
        for (int ks = 0; ks < 4; ks++) {
            uint32_t bh[4][4], bl[4][4];
            #pragma unroll
            for (int np = 0; np < 4; np++) {
                ldsm4(bh[np], smem_u32(&Ksh[(np * 16 + lkn) * 72 + ks * 16 + lkk]));
                ldsm4(bl[np], smem_u32(&Ksl[(np * 16 + lkn) * 72 + ks * 16 + lkk]));
            }
            #pragma unroll
            for (int np = 0; np < 4; np++) {
                mma16816(s[np * 2],     qa_h[ks], bh[np][0], bh[np][1]);
                mma16816(s[np * 2 + 1], qa_h[ks], bh[np][2], bh[np][3]);
            }
            #pragma unroll
            for (int np = 0; np < 4; np++) {
                mma16816(s[np * 2],     qa_l[ks], bh[np][0], bh[np][1]);
                mma16816(s[np * 2 + 1], qa_l[ks], bh[np][2], bh[np][3]);
            }
            #pragma unroll
            for (int np = 0; np < 4; np++) {
                mma16816(s[np * 2],     qa_h[ks], bl[np][0], bl[np][1]);
                mma16816(s[np * 2 + 1], qa_h[ks], bl[np][2], bl[np][3]);
            }
        }

        // ---- online softmax (quad max; l kept as per-thread partials) ----
        float mxA = -INFINITY, mxB = -INFINITY;
        #pragma unroll
        for (int j = 0; j < 8; j++) {
            mxA = fmaxf(mxA, fmaxf(s[j][0], s[j][1]));
            mxB = fmaxf(mxB, fmaxf(s[j][2], s[j][3]));
        }
        mxA = fmaxf(mxA, __shfl_xor_sync(0xffffffffu, mxA, 1));
        mxA = fmaxf(mxA, __shfl_xor_sync(0xffffffffu, mxA, 2));
        mxB = fmaxf(mxB, __shfl_xor_sync(0xffffffffu, mxB, 1));
        mxB = fmaxf(mxB, __shfl_xor_sync(0xffffffffu, mxB, 2));

        float mA_new = fmaxf(mA, mxA), mB_new = fmaxf(mB, mxB);
        float cA = exp2f(mA - mA_new), cB = exp2f(mB - mB_new);
        lA *= cA;  lB *= cB;
        mA = mA_new;  mB = mB_new;

        uint32_t pa_h[4][4], pa_l[4][4];
        #pragma unroll
        for (int jp = 0; jp < 4; jp++) {
            #pragma unroll
            for (int half = 0; half < 2; half++) {
                int t = jp * 2 + half;
                float p0 = exp2f(s[t][0] - mA_new);
                float p1 = exp2f(s[t][1] - mA_new);
                float p2 = exp2f(s[t][2] - mB_new);
                float p3 = exp2f(s[t][3] - mB_new);
                lA += p0 + p1;
                lB += p2 + p3;
                split_pack(p0, p1, pa_h[jp][half * 2 + 0], pa_l[jp][half * 2 + 0]);
                split_pack(p2, p3, pa_h[jp][half * 2 + 1], pa_l[jp][half * 2 + 1]);
            }
        }

        #pragma unroll
        for (int j = 0; j < 8; j++) {
            o[j][0] *= cA; o[j][1] *= cA;
            o[j][2] *= cB; o[j][3] *= cB;
        }

        // ---- O += P V, term-interleaved ----
        #pragma unroll
        for (int jp = 0; jp < 4; jp++) {
            uint32_t bh[4][4], bl[4][4];
            #pragma unroll
            for (int nv = 0; nv < 4; nv++) {
                ldsm4t(bh[nv], smem_u32(&Vsh[(jp * 16 + lvr) * 72 + nv * 16 + lvc]));
                ldsm4t(bl[nv], smem_u32(&Vsl[(jp * 16 + lvr) * 72 + nv * 16 + lvc]));
            }
            #pragma unroll
            for (int nv = 0; nv < 4; nv++) {
                mma16816(o[nv * 2],     pa_h[jp], bh[nv][0], bh[nv][1]);
                mma16816(o[nv * 2 + 1], pa_h[jp], bh[nv][2], bh[nv][3]);
            }
            #pragma unroll
            for (int nv = 0; nv < 4; nv++) {
                mma16816(o[nv * 2],     pa_l[jp], bh[nv][0], bh[nv][1]);
                mma16816(o[nv * 2 + 1], pa_l[jp], bh[nv][2], bh[nv][3]);
            }
            #pragma unroll
            for (int nv = 0; nv < 4; nv++) {
                mma16816(o[nv * 2],     pa_h[jp], bl[nv][0], bl[nv][1]);
                mma16816(o[nv * 2 + 1], pa_h[jp], bl[nv][2], bl[nv][3]);
            }
        }
        // no end-of-iter barrier: top-of-iter wait_group+bar orders buffer reuse
    }

    // ---- quad-reduce the deferred l partials, then epilogue ----
    lA += __shfl_xor_sync(0xffffffffu, lA, 1);
    lA += __shfl_xor_sync(0xffffffffu, lA, 2);
    lB += __shfl_xor_sync(0xffffffffu, lB, 1);
    lB += __shfl_xor_sync(0xffffffffu, lB, 2);

    const float iA = 1.f / lA, iB = 1.f / lB;
    const int row = q0 + warp * 16 + (lane >> 2);
    const int c0 = blockIdx.y * HD + (lane & 3) * 2;
    #pragma unroll
    for (int half = 0; half < 2; half++) {
        size_t tok = (size_t)blockIdx.z * SEQ + row + half * 8;
        __nv_bfloat16* base = a2 + tok * K3;
        float inv = half ? iB : iA;
        #pragma unroll
        for (int j = 0; j < 8; j++) {
            float a0 = o[j][half * 2 + 0] * inv;
            float a1 = o[j][half * 2 + 1] * inv;
            uint32_t hv, lv;
            split_pack(a0, a1, hv, lv);
            int cc = c0 + j * 8;
            *(uint32_t*)(base + cc)            = hv;
            *(uint32_t*)(base + DIM + cc)      = hv;
            *(uint32_t*)(base + 2 * DIM + cc)  = lv;
        }
    }
}

// ---------------------------------------------------------------------------

extern "C" void kernel_launch(void* const* d_in, const int* in_sizes, int n_in,
                              void* d_out, int out_size)
{
    const float* x      = (const float*)d_in[0];
    const float* W_qkv  = (const float*)d_in[1];
    const float* b_qkv  = (const float*)d_in[2];
    const float* W_proj = (const float*)d_in[3];
    const float* b_proj = (const float*)d_in[4];
    float* out = (float*)d_out;

    __nv_bfloat16 *a1, *b1, *a2, *b2;
    cudaGetSymbolAddress((void**)&a1, g_a1);
    cudaGetSymbolAddress((void**)&b1, g_b1);
    cudaGetSymbolAddress((void**)&a2, g_a2);
    cudaGetSymbolAddress((void**)&b2, g_b2);
    __nv_bfloat16 *qh, *ql, *kh, *kl, *vh, *vl;
    cudaGetSymbolAddress((void**)&qh, g_qh);
    cudaGetSymbolAddress((void**)&ql, g_ql);
    cudaGetSymbolAddress((void**)&kh, g_kh);
    cudaGetSymbolAddress((void**)&kl, g_kl);
    cudaGetSymbolAddress((void**)&vh, g_vh);
    cudaGetSymbolAddress((void**)&vl, g_vl);

    cudaFuncSetAttribute(gemm_ms<0>, cudaFuncAttributeMaxDynamicSharedMemorySize, GEMM_SMEM);
    cudaFuncSetAttribute(gemm_ms<1>, cudaFuncAttributeMaxDynamicSharedMemorySize, GEMM_SMEM);
    cudaFuncSetAttribute(attn_tc,    cudaFuncAttributeMaxDynamicSharedMemorySize, ATT_SMEM);

    // 1) splits for gemm1
    split_a<<<(M_TOT * DIM / 4) / 256, 256>>>((const float4*)x, a1, M_TOT, DIM);
    split_b<<<(DIM * K3 / 4) / 256, 256>>>((const float4*)W_qkv, b1, DIM, K3);

    // 2) qkv = x @ W_qkv + b_qkv, fused hi/lo head-major scatter (q *= QSCALE)
    {
        dim3 grid(K3 / GBN, M_TOT / 128);
        gemm_ms<1><<<grid, 128, GEMM_SMEM>>>(a1, b1, b_qkv, nullptr, K3);
    }

    // 3) attention, fused K-concat hi/lo epilogue -> a2
    {
        dim3 grid(SEQ / 64, NH, BATCH);
        attn_tc<<<grid, 128, ATT_SMEM>>>(qh, ql, kh, kl, vh, vl, a2);
    }

    // 4) W_proj split
    split_b<<<(DIM * DIM / 4) / 256, 256>>>((const float4*)W_proj, b2, DIM, DIM);

    // 5) out = attn @ W_proj + b_proj
    {
        dim3 grid(DIM / GBN, M_TOT / 128);
        gemm_ms<0><<<grid, 128, GEMM_SMEM>>>(a2, b2, b_proj, out, DIM);
    }
}